// round 17
// baseline (speedup 1.0000x reference)
#include <cuda_runtime.h>
#include <cstdint>

#define N_NODES 100000
#define N_EDGES 1600000
#define D 128
#define SPLIT_ROW 50048                 // = 1564 * 32
#define TILE_M 32
#define N_TILES_1 1564                  // rows [0, 50048)
#define N_TILES_2 1561                  // rows [50048, 100000) = 49952 rows
#define PERSIST_BLOCKS 304              // 2 CTAs x 152 SMs
#define SCAN_BLOCK 512
#define NB_SCAN ((N_NODES + SCAN_BLOCK - 1) / SCAN_BLOCK)   // 196

// ---- device scratch (allocation-free rule: __device__ globals) ----
__device__ float g_support[(size_t)N_NODES * D];
__device__ int   g_count2[2 * N_NODES];      // [0,N): total per dst, [N,2N): lo per dst
__device__ int   g_offset[N_NODES + 1];
__device__ int   g_bound[N_NODES];           // offset + n_lo  (lo/hi boundary)
__device__ int   g_cur_lo[N_NODES];
__device__ int   g_cur_hi[N_NODES];
__device__ int   g_blocksum[NB_SCAN];
__device__ uint2 g_edges[N_EDGES];           // {src, bits(w)}, dst-grouped, lo-then-hi
__device__ int   g_tile_ctr[2];              // dynamic tile queues (per GEMM half)

static_assert(NB_SCAN <= 256, "scan2 single block assumption");

// =================== CSR build (lo/hi partitioned) ===================
__global__ void hist_kernel(const int* __restrict__ esrc,
                            const int* __restrict__ edst)
{
    int i = blockIdx.x * blockDim.x + threadIdx.x;
    int stride = gridDim.x * blockDim.x;
    for (; i < N_EDGES; i += stride) {
        int d = edst[i];
        atomicAdd(&g_count2[d], 1);
        if (esrc[i] < SPLIT_ROW) atomicAdd(&g_count2[N_NODES + d], 1);
    }
}

__global__ void scan1_kernel()
{
    __shared__ int warp_sums[SCAN_BLOCK / 32];
    int tid = threadIdx.x;
    int gid = blockIdx.x * SCAN_BLOCK + tid;
    int v = (gid < N_NODES) ? g_count2[gid] : 0;

    int x = v;
    #pragma unroll
    for (int o = 1; o < 32; o <<= 1) {
        int y = __shfl_up_sync(0xFFFFFFFFu, x, o);
        if ((tid & 31) >= o) x += y;
    }
    if ((tid & 31) == 31) warp_sums[tid >> 5] = x;
    __syncthreads();
    if (tid < 32) {
        const int nw = SCAN_BLOCK / 32;
        int s = (tid < nw) ? warp_sums[tid] : 0;
        #pragma unroll
        for (int o = 1; o < 32; o <<= 1) {
            int y = __shfl_up_sync(0xFFFFFFFFu, s, o);
            if (tid >= o) s += y;
        }
        if (tid < nw) warp_sums[tid] = s;
    }
    __syncthreads();
    int base = (tid >= 32) ? warp_sums[(tid >> 5) - 1] : 0;
    int incl = x + base;
    if (gid < N_NODES) g_offset[gid] = incl - v;
    if (tid == SCAN_BLOCK - 1) g_blocksum[blockIdx.x] = incl;
}

__global__ void scan2_kernel()
{
    __shared__ int sh[256];
    int tid = threadIdx.x;
    int v = (tid < NB_SCAN) ? g_blocksum[tid] : 0;
    sh[tid] = v;
    __syncthreads();
    #pragma unroll
    for (int o = 1; o < 256; o <<= 1) {
        int y = (tid >= o) ? sh[tid - o] : 0;
        __syncthreads();
        sh[tid] += y;
        __syncthreads();
    }
    if (tid < NB_SCAN) g_blocksum[tid] = sh[tid] - v;
}

__global__ void scan3_kernel()
{
    int gid = blockIdx.x * SCAN_BLOCK + threadIdx.x;
    if (gid < N_NODES) {
        int o = g_offset[gid] + g_blocksum[blockIdx.x];
        int b = o + g_count2[N_NODES + gid];
        g_offset[gid] = o;
        g_bound[gid]  = b;
        g_cur_lo[gid] = o;
        g_cur_hi[gid] = b;
    }
    if (gid == 0) g_offset[N_NODES] = N_EDGES;
}

__global__ void scatter_kernel(const int* __restrict__ esrc,
                               const int* __restrict__ edst,
                               const float* __restrict__ ew)
{
    int i = blockIdx.x * blockDim.x + threadIdx.x;
    int stride = gridDim.x * blockDim.x;
    for (; i < N_EDGES; i += stride) {
        int d = edst[i];
        int s = esrc[i];
        int pos = (s < SPLIT_ROW) ? atomicAdd(&g_cur_lo[d], 1)
                                  : atomicAdd(&g_cur_hi[d], 1);
        g_edges[pos] = make_uint2((unsigned)s, __float_as_uint(ew[i]));
    }
}

// ---------------------------------------------------------------------------
// Persistent GEMM half: support[row_base + t*32 ...] = x @ W for n_tiles
// 32-row tiles (exact coverage, no bounds checks), dynamic per-half queue,
// register prefetch of the next x-tile. 256 threads: thread = 4 rows x 4 cols.
// smem 80 KB -> 2 CTAs/SM.
// ---------------------------------------------------------------------------
__global__ void __launch_bounds__(256, 2)
gemm_half_kernel(const float* __restrict__ x,
                 const float* __restrict__ W,
                 float* __restrict__ support,
                 int ctr_idx, int row_base, int n_tiles)
{
    extern __shared__ float smem[];
    float* Ws = smem;                  // [128][128] 64 KB
    float* xs = smem + D * D;          // [32][128]  16 KB
    __shared__ int s_next;

    int tid = threadIdx.x;
    int cg = tid & 31;    // cols cg*4..cg*4+3
    int rg = tid >> 5;    // rows rg*4..rg*4+3

    {
        const float4* Wg = (const float4*)W;
        float4* Wsh = (float4*)Ws;
        #pragma unroll
        for (int i = 0; i < 16; i++)
            Wsh[tid + i * 256] = Wg[tid + i * 256];
    }

    const float4* xg = (const float4*)x;
    float4* xs4 = (float4*)xs;

    if (tid == 0) s_next = atomicAdd(&g_tile_ctr[ctr_idx], 1);
    __syncthreads();
    int tile = s_next;

    float4 pre[4];                      // 32x128 tile = 1024 f4 / 256 thr
    if (tile < n_tiles) {
        #pragma unroll
        for (int i = 0; i < 4; i++) {
            int idx = tid + i * 256;    // 0..1023
            int r = idx >> 5, c4 = idx & 31;
            pre[i] = xg[(size_t)(row_base + tile * TILE_M + r) * 32 + c4];
        }
    }

    while (tile < n_tiles) {
        __syncthreads();
        if (tid == 0) s_next = atomicAdd(&g_tile_ctr[ctr_idx], 1);
        #pragma unroll
        for (int i = 0; i < 4; i++)
            xs4[tid + i * 256] = pre[i];
        __syncthreads();

        int ntile = s_next;
        if (ntile < n_tiles) {
            #pragma unroll
            for (int i = 0; i < 4; i++) {
                int idx = tid + i * 256;
                int r = idx >> 5, c4 = idx & 31;
                pre[i] = xg[(size_t)(row_base + ntile * TILE_M + r) * 32 + c4];
            }
        }

        float acc[4][4];
        #pragma unroll
        for (int r = 0; r < 4; r++)
            #pragma unroll
            for (int c = 0; c < 4; c++) acc[r][c] = 0.f;

        const float4* xrow4 = (const float4*)(xs + (size_t)(rg * 4) * D);
        const float4* Ws4   = (const float4*)Ws;

        #pragma unroll 4
        for (int k4 = 0; k4 < 32; k4++) {
            float4 w0 = Ws4[(k4 * 4 + 0) * 32 + cg];
            float4 w1 = Ws4[(k4 * 4 + 1) * 32 + cg];
            float4 w2 = Ws4[(k4 * 4 + 2) * 32 + cg];
            float4 w3 = Ws4[(k4 * 4 + 3) * 32 + cg];
            #pragma unroll
            for (int r = 0; r < 4; r++) {
                float4 xv = xrow4[r * 32 + k4];
                acc[r][0] += xv.x * w0.x; acc[r][1] += xv.x * w0.y;
                acc[r][2] += xv.x * w0.z; acc[r][3] += xv.x * w0.w;
                acc[r][0] += xv.y * w1.x; acc[r][1] += xv.y * w1.y;
                acc[r][2] += xv.y * w1.z; acc[r][3] += xv.y * w1.w;
                acc[r][0] += xv.z * w2.x; acc[r][1] += xv.z * w2.y;
                acc[r][2] += xv.z * w2.z; acc[r][3] += xv.z * w2.w;
                acc[r][0] += xv.w * w3.x; acc[r][1] += xv.w * w3.y;
                acc[r][2] += xv.w * w3.z; acc[r][3] += xv.w * w3.w;
            }
        }

        int m0 = row_base + tile * TILE_M;
        #pragma unroll
        for (int r = 0; r < 4; r++)
            *(float4*)&support[(size_t)(m0 + rg * 4 + r) * D + cg * 4] =
                make_float4(acc[r][0], acc[r][1], acc[r][2], acc[r][3]);

        tile = ntile;
    }
}

// ---------------------------------------------------------------------------
// Gather pass 1 (lo edges: src < SPLIT_ROW): out = bias + sum_lo
// ---------------------------------------------------------------------------
__global__ void gather_lo_kernel(const float* __restrict__ bias,
                                 float* __restrict__ out)
{
    int warp = (blockIdx.x * blockDim.x + threadIdx.x) >> 5;
    int lane = threadIdx.x & 31;
    if (warp >= N_NODES) return;

    int start = g_offset[warp];
    int end   = g_bound[warp];

    const float4* sup4 = (const float4*)g_support;
    float4 acc = __ldg(&((const float4*)bias)[lane]);

    for (int i = start; i < end; i += 32) {
        int n = end - i;
        if (n > 32) n = 32;
        uint2 em = make_uint2(0u, 0u);
        if (lane < n) em = g_edges[i + lane];
        for (int j = 0; j < n; j++) {
            unsigned s = __shfl_sync(0xFFFFFFFFu, em.x, j);
            float    w = __uint_as_float(__shfl_sync(0xFFFFFFFFu, em.y, j));
            float4 v = sup4[(size_t)s * (D / 4) + lane];
            acc.x += w * v.x;
            acc.y += w * v.y;
            acc.z += w * v.z;
            acc.w += w * v.w;
        }
    }
    ((float4*)out)[(size_t)warp * (D / 4) + lane] = acc;
}

// ---------------------------------------------------------------------------
// Gather pass 2 (hi edges: src >= SPLIT_ROW): out += sum_hi
// ---------------------------------------------------------------------------
__global__ void gather_hi_kernel(float* __restrict__ out)
{
    int warp = (blockIdx.x * blockDim.x + threadIdx.x) >> 5;
    int lane = threadIdx.x & 31;
    if (warp >= N_NODES) return;

    int start = g_bound[warp];
    int end   = g_offset[warp + 1];

    const float4* sup4 = (const float4*)g_support;
    float4 acc = ((const float4*)out)[(size_t)warp * (D / 4) + lane];

    for (int i = start; i < end; i += 32) {
        int n = end - i;
        if (n > 32) n = 32;
        uint2 em = make_uint2(0u, 0u);
        if (lane < n) em = g_edges[i + lane];
        for (int j = 0; j < n; j++) {
            unsigned s = __shfl_sync(0xFFFFFFFFu, em.x, j);
            float    w = __uint_as_float(__shfl_sync(0xFFFFFFFFu, em.y, j));
            float4 v = sup4[(size_t)s * (D / 4) + lane];
            acc.x += w * v.x;
            acc.y += w * v.y;
            acc.z += w * v.z;
            acc.w += w * v.w;
        }
    }
    ((float4*)out)[(size_t)warp * (D / 4) + lane] = acc;
}

// ---------------------------------------------------------------------------
// Launch topology (1 side stream + 3 events, per-call, never cached):
//   main : memset(ctrs) G1 |evG1| G2            [wait ev_join] gather_hi
//   side : [wait ev_fork] CSR chain [wait evG1] gather_lo |ev_join|
// gather_lo (L2-bound) co-schedules with G2 (FFMA-bound).
// ---------------------------------------------------------------------------
extern "C" void kernel_launch(void* const* d_in, const int* in_sizes, int n_in,
                              void* d_out, int out_size)
{
    const float* x    = (const float*)d_in[0];
    const int*   esrc = (const int*)d_in[1];
    const int*   edst = (const int*)d_in[2];
    const float* ew   = (const float*)d_in[3];
    const float* W    = (const float*)d_in[4];
    const float* bias = (const float*)d_in[5];
    float* out = (float*)d_out;

    void* countPtr;
    cudaGetSymbolAddress(&countPtr, g_count2);
    void* ctrPtr;
    cudaGetSymbolAddress(&ctrPtr, g_tile_ctr);
    float* support;
    cudaGetSymbolAddress((void**)&support, g_support);

    cudaStream_t main_s = 0;
    cudaStream_t side_s;
    cudaStreamCreateWithFlags(&side_s, cudaStreamNonBlocking);
    cudaEvent_t ev_fork, ev_g1, ev_join;
    cudaEventCreateWithFlags(&ev_fork, cudaEventDisableTiming);
    cudaEventCreateWithFlags(&ev_g1, cudaEventDisableTiming);
    cudaEventCreateWithFlags(&ev_join, cudaEventDisableTiming);

    const int gather_blocks = (N_NODES + 7) / 8;   // 8 warps per 256-thr block
    static const int smem_bytes = (D * D + TILE_M * D) * (int)sizeof(float); // 80 KB
    cudaFuncSetAttribute(gemm_half_kernel,
                         cudaFuncAttributeMaxDynamicSharedMemorySize, smem_bytes);

    // ---- fork ----
    cudaEventRecord(ev_fork, main_s);
    cudaStreamWaitEvent(side_s, ev_fork, 0);

    // side: CSR build chain (lo/hi partitioned)
    cudaMemsetAsync(countPtr, 0, 2 * N_NODES * sizeof(int), side_s);
    hist_kernel<<<1024, 256, 0, side_s>>>(esrc, edst);
    scan1_kernel<<<NB_SCAN, SCAN_BLOCK, 0, side_s>>>();
    scan2_kernel<<<1, 256, 0, side_s>>>();
    scan3_kernel<<<NB_SCAN, SCAN_BLOCK, 0, side_s>>>();
    scatter_kernel<<<1024, 256, 0, side_s>>>(esrc, edst, ew);

    // main: GEMM half 1 (rows [0, SPLIT_ROW))
    cudaMemsetAsync(ctrPtr, 0, 2 * sizeof(int), main_s);
    gemm_half_kernel<<<PERSIST_BLOCKS, 256, smem_bytes, main_s>>>(
        x, W, support, 0, 0, N_TILES_1);
    cudaEventRecord(ev_g1, main_s);

    // main: GEMM half 2 (rows [SPLIT_ROW, N))  — overlaps gather_lo
    gemm_half_kernel<<<PERSIST_BLOCKS, 256, smem_bytes, main_s>>>(
        x, W, support, 1, SPLIT_ROW, N_TILES_2);

    // side: gather_lo after CSR (program order) and after G1 (event)
    cudaStreamWaitEvent(side_s, ev_g1, 0);
    gather_lo_kernel<<<gather_blocks, 256, 0, side_s>>>(bias, out);
    cudaEventRecord(ev_join, side_s);

    // main: gather_hi after G2 (program order) and gather_lo (event)
    cudaStreamWaitEvent(main_s, ev_join, 0);
    gather_hi_kernel<<<gather_blocks, 256, 0, main_s>>>(out);
}